// round 16
// baseline (speedup 1.0000x reference)
#include <cuda_runtime.h>
#include <cuda_bf16.h>
#include <cuda_fp16.h>
#include <cstdint>

#define Bz    2
#define Sq    2048
#define DIM   1024
#define Hn    16
#define DHd   64
#define INNER 1024
#define TOK   4096

// ---------------------------------------------------------------------------
// Scratch (device globals). Fragment arrays are uint32 (packed 16-bit x2).
// ---------------------------------------------------------------------------
__device__ uint32_t g_xn_h[TOK*DIM/2],     g_xn_l[TOK*DIM/2];   // bf16 hi/lo A-frags
__device__ uint32_t g_xn16[TOK*DIM/2];                          // fp16 single A-frags
__device__ uint32_t g_wqk_h[DIM*2048/2],   g_wqk_l[DIM*2048/2]; // Wq|Wk bf16 B-frags
__device__ uint32_t g_wv16[DIM*INNER/2];                        // Wv fp16 B-frags
__device__ uint32_t g_wo16[INNER*DIM/2];                        // Wo fp16 B-frags
__device__ uint32_t g_qf_h[TOK*INNER/2],   g_qf_l[TOK*INNER/2]; // fp16 hi/lo
__device__ uint32_t g_kf_h[TOK*INNER/2],   g_kf_l[TOK*INNER/2]; // fp16 hi/lo
__device__ uint32_t g_vf  [TOK*INNER/2];                        // fp16 single
__device__ uint32_t g_ao16[TOK*INNER/2];                        // attn out fp16 A-frags

#define LOG2E 1.4426950408889634f

// ---------------------------------------------------------------------------
// Helpers
// ---------------------------------------------------------------------------
__device__ __forceinline__ uint32_t smem_u32(const void* p) {
    uint32_t a;
    asm("{ .reg .u64 t; cvta.to.shared.u64 t, %1; cvt.u32.u64 %0, t; }" : "=r"(a) : "l"(p));
    return a;
}
__device__ __forceinline__ uint32_t pkbf(float a, float b) {
    return (uint32_t)__bfloat16_as_ushort(__float2bfloat16_rn(a)) |
           ((uint32_t)__bfloat16_as_ushort(__float2bfloat16_rn(b)) << 16);
}
__device__ __forceinline__ void splitbf(float a, float b, uint32_t& hi, uint32_t& lo) {
    __nv_bfloat16 ha = __float2bfloat16_rn(a), hb = __float2bfloat16_rn(b);
    hi = (uint32_t)__bfloat16_as_ushort(ha) | ((uint32_t)__bfloat16_as_ushort(hb) << 16);
    lo = pkbf(a - __bfloat162float(ha), b - __bfloat162float(hb));
}
__device__ __forceinline__ uint32_t pkh2(float a, float b) {
    __half2 h = __floats2half2_rn(a, b);
    return *(uint32_t*)&h;
}
__device__ __forceinline__ void splitf16(float a, float b, uint32_t& hi, uint32_t& lo) {
    __half ha = __float2half_rn(a), hb = __float2half_rn(b);
    __half2 hp = __halves2half2(ha, hb);
    hi = *(uint32_t*)&hp;
    lo = pkh2(a - __half2float(ha), b - __half2float(hb));
}
__device__ __forceinline__ float ex2(float x) {
    float y;
    asm("ex2.approx.f32 %0, %1;" : "=f"(y) : "f"(x));
    return y;
}
__device__ __forceinline__ uint32_t ex2h2(float a, float b) {
    uint32_t r;
    asm("{ .reg .b32 t; cvt.rn.f16x2.f32 t, %2, %1; ex2.approx.f16x2 %0, t; }"
        : "=r"(r) : "f"(a), "f"(b));
    return r;
}
__device__ __forceinline__ uint32_t hadd2u(uint32_t a, uint32_t b) {
    uint32_t r;
    asm("add.f16x2 %0, %1, %2;" : "=r"(r) : "r"(a), "r"(b));
    return r;
}
__device__ __forceinline__ float2 h22f2(uint32_t h) {
    __half2 hh = *(__half2*)&h;
    return __half22float2(hh);
}
__device__ __forceinline__ void mma_bf(float* c, const uint32_t* a, const uint32_t* b) {
    asm volatile(
        "mma.sync.aligned.m16n8k16.row.col.f32.bf16.bf16.f32 "
        "{%0,%1,%2,%3}, {%4,%5,%6,%7}, {%8,%9}, {%0,%1,%2,%3};"
        : "+f"(c[0]), "+f"(c[1]), "+f"(c[2]), "+f"(c[3])
        : "r"(a[0]), "r"(a[1]), "r"(a[2]), "r"(a[3]), "r"(b[0]), "r"(b[1]));
}
__device__ __forceinline__ void mma_f16(float* c, const uint32_t* a, const uint32_t* b) {
    asm volatile(
        "mma.sync.aligned.m16n8k16.row.col.f32.f16.f16.f32 "
        "{%0,%1,%2,%3}, {%4,%5,%6,%7}, {%8,%9}, {%0,%1,%2,%3};"
        : "+f"(c[0]), "+f"(c[1]), "+f"(c[2]), "+f"(c[3])
        : "r"(a[0]), "r"(a[1]), "r"(a[2]), "r"(a[3]), "r"(b[0]), "r"(b[1]));
}
__device__ __forceinline__ void cpa16(uint32_t saddr, const void* gptr) {
    asm volatile("cp.async.cg.shared.global [%0], [%1], 16;" :: "r"(saddr), "l"(gptr) : "memory");
}
__device__ __forceinline__ void cp_commit() { asm volatile("cp.async.commit_group;" ::: "memory"); }
template <int N> __device__ __forceinline__ void cp_wait() {
    asm volatile("cp.async.wait_group %0;" :: "n"(N) : "memory");
}

// ---------------------------------------------------------------------------
// 1) Prep: blocks [0,4096) LayerNorm; [4096,5120) coalesced weight frags.
// ---------------------------------------------------------------------------
__global__ void __launch_bounds__(256) prep_kernel(const float* __restrict__ x,
                                                   const float* __restrict__ w,
                                                   const float* __restrict__ bias,
                                                   uint32_t* __restrict__ xh,
                                                   uint32_t* __restrict__ xl,
                                                   uint32_t* __restrict__ x16,
                                                   const float* __restrict__ Wq,
                                                   const float* __restrict__ Wkv,
                                                   const float* __restrict__ Wo,
                                                   uint32_t* __restrict__ wqkh,
                                                   uint32_t* __restrict__ wqkl,
                                                   uint32_t* __restrict__ wv16,
                                                   uint32_t* __restrict__ wo16) {
    const int bid = blockIdx.x;
    if (bid >= TOK) {
        const int r = bid - TOK;
        const int mat = r >> 8;                // 0=Wq 1=Wk 2=Wv 3=Wo
        const int warp = threadIdx.x >> 5, lane = threadIdx.x & 31;
        const int gw = (r & 255) * 8 + warp;
        const int pb  = gw & 63;
        const int nt0 = (gw >> 6) << 2;
        const int ntl = lane >> 3, g = lane & 7;
        const int nt  = nt0 + ntl;
        const int n_local = nt * 8 + g;

        const float* src;
        int stride, col;
        if (mat == 0)      { src = Wq;  stride = 1024; col = n_local; }
        else if (mat == 1) { src = Wkv; stride = 2048; col = n_local; }
        else if (mat == 2) { src = Wkv; stride = 2048; col = 1024 + n_local; }
        else               { src = Wo;  stride = 1024; col = n_local; }

        float v[16];
#pragma unroll
        for (int i = 0; i < 16; i++)
            v[i] = src[(size_t)(16 * pb + i) * stride + col];

        if (mat <= 1) {
            uint32_t hiw[8], low[8];
#pragma unroll
            for (int o = 0; o < 8; o++) {
                const int pl = ((o & 1) << 2) + (o >> 1);
                splitbf(v[2 * pl], v[2 * pl + 1], hiw[o], low[o]);
            }
            const int out_nt = (mat == 0 ? 0 : 128) + nt;
            const size_t base = ((size_t)(out_nt * 64 + pb)) * 64 + g * 8;
            *(uint4*)(wqkh + base)     = make_uint4(hiw[0], hiw[1], hiw[2], hiw[3]);
            *(uint4*)(wqkh + base + 4) = make_uint4(hiw[4], hiw[5], hiw[6], hiw[7]);
            *(uint4*)(wqkl + base)     = make_uint4(low[0], low[1], low[2], low[3]);
            *(uint4*)(wqkl + base + 4) = make_uint4(low[4], low[5], low[6], low[7]);
        } else {
            uint32_t wd[8];
#pragma unroll
            for (int o = 0; o < 8; o++) {
                const int pl = ((o & 1) << 2) + (o >> 1);
                wd[o] = pkh2(v[2 * pl], v[2 * pl + 1]);
            }
            uint32_t* dst = (mat == 2) ? wv16 : wo16;
            const size_t base = ((size_t)(nt * 64 + pb)) * 64 + g * 8;
            *(uint4*)(dst + base)     = make_uint4(wd[0], wd[1], wd[2], wd[3]);
            *(uint4*)(dst + base + 4) = make_uint4(wd[4], wd[5], wd[6], wd[7]);
        }
        return;
    }
    const int row = bid;
    const float* xr = x + (size_t)row * DIM;
    float2 v[2];
    v[0] = *(const float2*)(xr + 2 * threadIdx.x);
    v[1] = *(const float2*)(xr + 2 * (threadIdx.x + 256));
    float s  = v[0].x + v[0].y + v[1].x + v[1].y;
    float sq = v[0].x * v[0].x + v[0].y * v[0].y + v[1].x * v[1].x + v[1].y * v[1].y;
#pragma unroll
    for (int off = 16; off; off >>= 1) {
        s  += __shfl_xor_sync(0xffffffffu, s, off);
        sq += __shfl_xor_sync(0xffffffffu, sq, off);
    }
    __shared__ float red[2][8];
    const int warp = threadIdx.x >> 5, lane = threadIdx.x & 31;
    if (lane == 0) { red[0][warp] = s; red[1][warp] = sq; }
    __syncthreads();
    float ts = 0.f, tq2 = 0.f;
#pragma unroll
    for (int i = 0; i < 8; i++) { ts += red[0][i]; tq2 += red[1][i]; }
    const float mean = ts * (1.0f / DIM);
    const float var  = tq2 * (1.0f / DIM) - mean * mean;
    const float rstd = rsqrtf(var + 1e-5f);
    const int mt = row >> 4, mr = row & 15, g = mr & 7, hih = mr >> 3;
#pragma unroll
    for (int i = 0; i < 2; i++) {
        const int p = threadIdx.x + i * 256;
        const float2 wv = *(const float2*)(w + 2 * p);
        const float2 bv = *(const float2*)(bias + 2 * p);
        const float y0 = wv.x * (v[i].x - mean) * rstd + bv.x;
        const float y1 = wv.y * (v[i].y - mean) * rstd + bv.y;
        const int ks = p >> 3, c = p & 7, tq = c & 3, ch = c >> 2;
        const size_t idx = ((size_t)(mt * 64 + ks)) * 128 + (g * 4 + tq) * 4 + hih + 2 * ch;
        uint32_t hi, lo;
        splitbf(y0, y1, hi, lo);
        xh[idx] = hi; xl[idx] = lo;
        x16[idx] = pkh2(y0, y1);
    }
}

// ---------------------------------------------------------------------------
// 2) Fused projection + RMSNorm + fragment emission.
//    blockIdx.x < 16 : QK bf16x3 GEMM -> rms epilogue -> qf/kf frags
//    blockIdx.x >= 16: V fp16 GEMM -> smem transpose -> vf frags
// ---------------------------------------------------------------------------
__global__ void __launch_bounds__(256, 2) proj_fused(const uint32_t* __restrict__ Ah,
                                                     const uint32_t* __restrict__ Al,
                                                     const uint32_t* __restrict__ A16,
                                                     const uint32_t* __restrict__ Bh,
                                                     const uint32_t* __restrict__ Bl,
                                                     const uint32_t* __restrict__ Bv,
                                                     const float* __restrict__ qg,
                                                     const float* __restrict__ kg,
                                                     uint32_t* __restrict__ qfh,
                                                     uint32_t* __restrict__ qfl,
                                                     uint32_t* __restrict__ kfh,
                                                     uint32_t* __restrict__ kfl,
                                                     uint32_t* __restrict__ vf) {
    extern __shared__ uint32_t sm[];
    const int tid = threadIdx.x, wid = tid >> 5, lane = tid & 31;
    const int wr = wid >> 2, wc = wid & 3, g = lane >> 2, tq = lane & 3;
    const int bm = blockIdx.y * 128;
    const int b  = bm >> 11;
    const int sb = bm & 2047;
    const uint32_t sbase = smem_u32(sm);
    const int KS = 64;   // K = 1024

    float acc[4][4][4];
#pragma unroll
    for (int i = 0; i < 4; i++)
#pragma unroll
        for (int j = 0; j < 4; j++)
#pragma unroll
            for (int e = 0; e < 4; e++) acc[i][j][e] = 0.f;

    if (blockIdx.x < 16) {
        // ================= QK bf16x3 mainloop (BK=32, 2-stage) ============
        const int bn = blockIdx.x * 128;
        const uint32_t* Ah0 = Ah + (size_t)(bm >> 4) * KS * 128;
        const uint32_t* Al0 = Al + (size_t)(bm >> 4) * KS * 128;
        const uint32_t* Bh0 = Bh + (size_t)(bn >> 3) * KS * 64;
        const uint32_t* Bl0 = Bl + (size_t)(bn >> 3) * KS * 64;

#define G_ISSUE(S, BUF) do {                                                        \
    const uint32_t sb_ = sbase + (uint32_t)(BUF) * 32768u;                          \
    _Pragma("unroll")                                                               \
    for (int i_ = 0; i_ < 2; i_++) {                                                \
        const int f_ = tid + i_ * 256;                                              \
        const int mt_ = f_ >> 6, wA_ = (4 * f_) & 255;                              \
        const int ksA_ = wA_ >> 7, frA_ = wA_ & 127;                                \
        const size_t oa_ = ((size_t)mt_ * KS + (S) * 2 + ksA_) * 128 + frA_;        \
        cpa16(sb_ + f_ * 16u,           Ah0 + oa_);                                 \
        cpa16(sb_ + 8192u + f_ * 16u,   Al0 + oa_);                                 \
        const int nt_ = f_ >> 5, wB_ = (4 * f_) & 127;                              \
        const int ksB_ = wB_ >> 6, frB_ = wB_ & 63;                                 \
        const size_t ob_ = ((size_t)nt_ * KS + (S) * 2 + ksB_) * 64 + frB_;         \
        cpa16(sb_ + 16384u + f_ * 16u,  Bh0 + ob_);                                 \
        cpa16(sb_ + 24576u + f_ * 16u,  Bl0 + ob_);                                 \
    }                                                                               \
    cp_commit();                                                                    \
} while (0)

        G_ISSUE(0, 0);
        int buf = 0;
        for (int s = 0; s < 32; s++) {
            if (s + 1 < 32) { G_ISSUE(s + 1, buf ^ 1); cp_wait<1>(); }
            else            { cp_wait<0>(); }
            __syncthreads();
            const uint32_t* S0 = sm + buf * 8192;
#pragma unroll
            for (int ksl = 0; ksl < 2; ksl++) {
                uint4 ah[4], al[4];
                uint2 bh2[4], bl2[4];
#pragma unroll
                for (int i = 0; i < 4; i++) {
                    const int mt = wr * 4 + i;
                    ah[i] = *(const uint4*)(S0 + (mt * 2 + ksl) * 128 + (g * 4 + tq) * 4);
                    al[i] = *(const uint4*)(S0 + 2048 + (mt * 2 + ksl) * 128 + (g * 4 + tq) * 4);
                }
#pragma unroll
                for (int j = 0; j < 4; j++) {
                    const int nt = wc * 4 + j;
                    bh2[j] = *(const uint2*)(S0 + 4096 + (nt * 2 + ksl) * 64 + (g * 4 + tq) * 2);
                    bl2[j] = *(const uint2*)(S0 + 6144 + (nt * 2 + ksl) * 64 + (g * 4 + tq) * 2);
                }
#pragma unroll
                for (int i = 0; i < 4; i++)
#pragma unroll
                    for (int j = 0; j < 4; j++) {
                        mma_bf(acc[i][j], (const uint32_t*)&ah[i], (const uint32_t*)&bh2[j]);
                        mma_bf(acc[i][j], (const uint32_t*)&ah[i], (const uint32_t*)&bl2[j]);
                        mma_bf(acc[i][j], (const uint32_t*)&al[i], (const uint32_t*)&bh2[j]);
                    }
            }
            __syncthreads();
            buf ^= 1;
        }
#undef G_ISSUE

        // ================= fused RMSNorm epilogue =========================
        float* part = (float*)sm;   // [4][128]
        float psum[4][2];
#pragma unroll
        for (int i = 0; i < 4; i++)
#pragma unroll
            for (int hih = 0; hih < 2; hih++) {
                float p = 0.f;
#pragma unroll
                for (int j = 0; j < 4; j++)
                    p += acc[i][j][2 * hih] * acc[i][j][2 * hih] +
                         acc[i][j][2 * hih + 1] * acc[i][j][2 * hih + 1];
                p += __shfl_xor_sync(0xffffffffu, p, 1);
                p += __shfl_xor_sync(0xffffffffu, p, 2);
                psum[i][hih] = p;
            }
        if (tq == 0) {
#pragma unroll
            for (int i = 0; i < 4; i++)
#pragma unroll
                for (int hih = 0; hih < 2; hih++)
                    part[wc * 128 + wr * 64 + i * 16 + g + 8 * hih] = psum[i][hih];
        }
        __syncthreads();
        float rsq[4][2];
#pragma unroll
        for (int i = 0; i < 4; i++)
#pragma unroll
            for (int hih = 0; hih < 2; hih++) {
                const int row = wr * 64 + i * 16 + g + 8 * hih;
                const float ss = part[wc * 128 + row] + part[(wc ^ 1) * 128 + row];
                rsq[i][hih] = rsqrtf(ss * (1.0f / 64.0f) + 1e-8f);
            }

        const bool isQ = (bn < 1024);
        const int h = ((isQ ? bn : bn - 1024) >> 6) + (wc >> 1);
        const int bh = b * 16 + h;

        if (isQ) {
#pragma unroll
            for (int i = 0; i < 4; i++) {
                const int mt = (sb >> 4) + wr * 4 + i;
#pragma unroll
                for (int ksl = 0; ksl < 2; ksl++) {
                    const int ks = (wc & 1) * 2 + ksl;
                    uint32_t hw[4], lw[4];
#pragma unroll
                    for (int w2 = 0; w2 < 4; w2++) {
                        const int hih = w2 & 1, ch = w2 >> 1;
                        const int j = 2 * ksl + ch;
                        const int dim = (wc & 1) * 32 + j * 8 + 2 * tq;
                        const float2 gv = *(const float2*)(qg + h * 64 + dim);
                        const float r = rsq[i][hih] * (8.0f * LOG2E);
                        splitf16(acc[i][j][2 * hih] * r * gv.x,
                                 acc[i][j][2 * hih + 1] * r * gv.y, hw[w2], lw[w2]);
                    }
                    const size_t base = ((size_t)((bh * 128 + mt) * 4 + ks)) * 128 + lane * 4;
                    *(uint4*)(qfh + base) = make_uint4(hw[0], hw[1], hw[2], hw[3]);
                    *(uint4*)(qfl + base) = make_uint4(lw[0], lw[1], lw[2], lw[3]);
                }
            }
        } else {
#pragma unroll
            for (int i = 0; i < 4; i++)
#pragma unroll
                for (int hih = 0; hih < 2; hih++) {
                    const int nt = (sb >> 3) + (wr * 4 + i) * 2 + hih;
#pragma unroll
                    for (int ksl = 0; ksl < 2; ksl++) {
                        const int ks = (wc & 1) * 2 + ksl;
                        uint32_t hw[2], lw[2];
#pragma unroll
                        for (int ch = 0; ch < 2; ch++) {
                            const int j = 2 * ksl + ch;
                            const int dim = (wc & 1) * 32 + j * 8 + 2 * tq;
                            const float2 gv = *(const float2*)(kg + h * 64 + dim);
                            const float r = rsq[i][hih] * 8.0f;
                            splitf16(acc[i][j][2 * hih] * r * gv.x,
                                     acc[i][j][2 * hih + 1] * r * gv.y, hw[ch], lw[ch]);
                        }
                        const size_t base = ((size_t)((bh * 256 + nt) * 4 + ks)) * 64 + lane * 2;
                        *(uint2*)(kfh + base) = make_uint2(hw[0], hw[1]);
                        *(uint2*)(kfl + base) = make_uint2(lw[0], lw[1]);
                    }
                }
        }
    } else {
        // ================= V fp16 mainloop (BK=64, 2-stage) ===============
        const int bn = (blockIdx.x - 16) * 128;
        const uint32_t* A0g = A16 + (size_t)(bm >> 4) * KS * 128;
        const uint32_t* B0g = Bv + (size_t)(bn >> 3) * KS * 64;

#define F_ISSUE(S, BUF) do {                                                        \
    const uint32_t sb_ = sbase + (uint32_t)(BUF) * 32768u;                          \
    _Pragma("unroll")                                                               \
    for (int i_ = 0; i_ < 4; i_++) {                                                \
        const int f_ = tid + i_ * 256;                                              \
        const int mt_ = f_ >> 7, wA_ = (4 * f_) & 511;                              \
        const int ksA_ = wA_ >> 7, frA_ = wA_ & 127;                                \
        const size_t oa_ = ((size_t)mt_ * KS + (S) * 4 + ksA_) * 128 + frA_;        \
        cpa16(sb_ + f_ * 16u, A0g + oa_);                                           \
        const int nt_ = f_ >> 6, wB_ = (4 * f_) & 255;                              \
        const int ksB_ = wB_ >> 6, frB_ = wB_ & 63;                                 \
        const size_t ob_ = ((size_t)nt_ * KS + (S) * 4 + ksB_) * 64 + frB_;         \
        cpa16(sb_ + 16384u + f_ * 16u, B0g + ob_);                                  \
    }                                                                               \
    cp_commit();                                                                    \
} while (0)

        F_ISSUE(0, 0);
        int buf = 0;
        for (int s = 0; s < 16; s++) {
            if (s + 1 < 16) { F_ISSUE(s + 1, buf ^ 1); cp_wait<1>(); }
            else            { cp_wait<0>(); }
            __syncthreads();
            const uint32_t* S0 = sm + buf * 8192;
#pragma unroll
            for (int ksl = 0; ksl < 4; ksl++) {
                uint4 a[4];
                uint2 b2[4];
#pragma unroll
                for (int i = 0; i < 4; i++)
                    a[i] = *(const uint4*)(S0 + ((wr * 4 + i) * 4 + ksl) * 128 + (g * 4 + tq) * 4);
#pragma unroll
                for (int j = 0; j < 4; j++)
                    b2[j] = *(const uint2*)(S0 + 4096 + ((wc * 4 + j) * 4 + ksl) * 64 + (g * 4 + tq) * 2);
#pragma unroll
                for (int i = 0; i < 4; i++)
#pragma unroll
                    for (int j = 0; j < 4; j++)
                        mma_f16(acc[i][j], (const uint32_t*)&a[i], (const uint32_t*)&b2[j]);
            }
            __syncthreads();
            buf ^= 1;
        }
#undef F_ISSUE

        // ================= V transpose epilogue -> vf B-frags =============
        __syncthreads();
        __half* vsm = (__half*)sm;     // [128][136]
#pragma unroll
        for (int i = 0; i < 4; i++)
#pragma unroll
            for (int j = 0; j < 4; j++)
#pragma unroll
                for (int e = 0; e < 4; e++) {
                    const int row = wr * 64 + i * 16 + g + 8 * (e >> 1);
                    const int col = wc * 32 + j * 8 + 2 * tq + (e & 1);
                    vsm[row * 136 + col] = __float2half_rn(acc[i][j][e]);
                }
        __syncthreads();
        const int h0 = bn >> 6;
        const int ksv = (sb >> 4) + wid;
        const int dl = lane >> 2, tv = lane & 3;
#pragma unroll
        for (int hh = 0; hh < 2; hh++) {
            const int bh = b * 16 + h0 + hh;
#pragma unroll
            for (int ntd = 0; ntd < 8; ntd++) {
                uint32_t w2[2];
#pragma unroll
                for (int rv = 0; rv < 2; rv++) {
                    const int rloc = 16 * wid + 8 * rv + 2 * tv;
                    const int col = hh * 64 + ntd * 8 + dl;
                    const __half va = vsm[rloc * 136 + col];
                    const __half vb = vsm[(rloc + 1) * 136 + col];
                    const __half2 hp = __halves2half2(va, vb);
                    w2[rv] = *(const uint32_t*)&hp;
                }
                const size_t base = ((size_t)((bh * 128 + ksv) * 8 + ntd)) * 64 + lane * 2;
                *(uint2*)(vf + base) = make_uint2(w2[0], w2[1]);
            }
        }
    }
}

// ---------------------------------------------------------------------------
// 3) Output projection: fp16-single GEMM, fp32 C.
// ---------------------------------------------------------------------------
__global__ void __launch_bounds__(256, 2) gemm_f16s(const uint32_t* __restrict__ Af,
                                                    const uint32_t* __restrict__ Bf,
                                                    float* __restrict__ C,
                                                    int N, int K) {
    extern __shared__ uint32_t sm[];
    const int tid = threadIdx.x, wid = tid >> 5, lane = tid & 31;
    const int wr = wid >> 2, wc = wid & 3, g = lane >> 2, tq = lane & 3;
    const int bm = blockIdx.y * 128, bn = blockIdx.x * 128;
    const int KS = K >> 4, NSTG = K >> 6;
    const uint32_t sbase = smem_u32(sm);

    const uint32_t* A0g = Af + (size_t)(bm >> 4) * KS * 128;
    const uint32_t* B0g = Bf + (size_t)(bn >> 3) * KS * 64;

    float acc[4][4][4];
#pragma unroll
    for (int i = 0; i < 4; i++)
#pragma unroll
        for (int j = 0; j < 4; j++)
#pragma unroll
            for (int e = 0; e < 4; e++) acc[i][j][e] = 0.f;

#define F_ISSUE(S, BUF) do {                                                        \
    const uint32_t sb_ = sbase + (uint32_t)(BUF) * 32768u;                          \
    _Pragma("unroll")                                                               \
    for (int i_ = 0; i_ < 4; i_++) {                                                \
        const int f_ = tid + i_ * 256;                                              \
        const int mt_ = f_ >> 7, wA_ = (4 * f_) & 511;                              \
        const int ksA_ = wA_ >> 7, frA_ = wA_ & 127;                                \
        const size_t oa_ = ((size_t)mt_ * KS + (S) * 4 + ksA_) * 128 + frA_;        \
        cpa16(sb_ + f_ * 16u, A0g + oa_);                                           \
        const int nt_ = f_ >> 6, wB_ = (4 * f_) & 255;                              \
        const int ksB_ = wB_ >> 6, frB_ = wB_ & 63;                                 \
        const size_t ob_ = ((size_t)nt_ * KS + (S) * 4 + ksB_) * 64 + frB_;         \
        cpa16(sb_ + 16384u + f_ * 16u, B0g + ob_);                                  \
    }                                                                               \
    cp_commit();                                                                    \
} while (0)

    F_ISSUE(0, 0);
    int buf = 0;
    for (int s = 0; s < NSTG; s++) {
        if (s + 1 < NSTG) { F_ISSUE(s + 1, buf ^ 1); cp_wait<1>(); }
        else              { cp_wait<0>(); }
        __syncthreads();
        const uint32_t* S0 = sm + buf * 8192;
#pragma unroll
        for (int ksl = 0; ksl < 4; ksl++) {
            uint4 a[4];
            uint2 b2[4];
#pragma unroll
            for (int i = 0; i < 4; i++)
                a[i] = *(const uint4*)(S0 + ((wr * 4 + i) * 4 + ksl) * 128 + (g * 4 + tq) * 4);
#pragma unroll
            for (int j = 0; j < 4; j++)
                b2[j] = *(const uint2*)(S0 + 4096 + ((wc * 4 + j) * 4 + ksl) * 64 + (g * 4 + tq) * 2);
#pragma unroll
            for (int i = 0; i < 4; i++)
#pragma unroll
                for (int j = 0; j < 4; j++)
                    mma_f16(acc[i][j], (const uint32_t*)&a[i], (const uint32_t*)&b2[j]);
        }
        __syncthreads();
        buf ^= 1;
    }
#undef F_ISSUE

#pragma unroll
    for (int i = 0; i < 4; i++) {
        const int r0 = bm + (wr * 4 + i) * 16 + g;
#pragma unroll
        for (int j = 0; j < 4; j++) {
            const int c0 = bn + (wc * 4 + j) * 8 + 2 * tq;
            *(float2*)(C + (size_t)r0 * N + c0)       = make_float2(acc[i][j][0], acc[i][j][1]);
            *(float2*)(C + (size_t)(r0 + 8) * N + c0) = make_float2(acc[i][j][2], acc[i][j][3]);
        }
    }
}

// ---------------------------------------------------------------------------
// 4) Flash attention (R13 structure, unchanged).
// ---------------------------------------------------------------------------
__global__ void __launch_bounds__(128, 4) attn_bf(const uint32_t* __restrict__ Qh,
                                                  const uint32_t* __restrict__ Ql,
                                                  const uint32_t* __restrict__ Kh,
                                                  const uint32_t* __restrict__ Kl,
                                                  const uint32_t* __restrict__ Vf,
                                                  uint32_t* __restrict__ O16) {
    extern __shared__ uint32_t sm[];
    const int tid = threadIdx.x, warp = tid >> 5, lane = tid & 31;
    const int g = lane >> 2, tq = lane & 3;
    const int bh = blockIdx.y, h = bh & 15;
    const uint32_t sbase = smem_u32(sm);

    uint4 qh_[4], ql_[4];
    {
        const size_t qb = ((size_t)(bh * 128 + blockIdx.x * 4 + warp)) * 4;
#pragma unroll
        for (int ks = 0; ks < 4; ks++) {
            qh_[ks] = *(const uint4*)(Qh + (qb + ks) * 128 + (g * 4 + tq) * 4);
            ql_[ks] = *(const uint4*)(Ql + (qb + ks) * 128 + (g * 4 + tq) * 4);
        }
    }

    const uint32_t* Kh0 = Kh + (size_t)bh * 65536;
    const uint32_t* Kl0 = Kl + (size_t)bh * 65536;
    const uint32_t* Vf0 = Vf + (size_t)bh * 65536;

    float oacc[8][4];
#pragma unroll
    for (int j = 0; j < 8; j++)
#pragma unroll
        for (int e = 0; e < 4; e++) oacc[j][e] = 0.f;
    float m0 = -1e30f, m1 = -1e30f, l0 = 0.f, l1 = 0.f;

#define A_ISSUE(T, BUF) do {                                                  \
    const uint32_t sb_ = sbase + (uint32_t)(BUF) * 24576u;                    \
    _Pragma("unroll")                                                         \
    for (int i_ = 0; i_ < 4; i_++) {                                          \
        const int f_ = tid + i_ * 128;                                        \
        const size_t o_ = (size_t)(T) * 2048 + 4 * f_;                        \
        cpa16(sb_ + f_ * 16u,          Kh0 + o_);                             \
        cpa16(sb_ + 8192u + f_ * 16u,  Kl0 + o_);                             \
        cpa16(sb_ + 16384u + f_ * 16u, Vf0 + o_);                             \
    }                                                                         \
    cp_commit();                                                              \
} while (0)

    A_ISSUE(0, 0);
    int buf = 0;
    const int NT = Sq / 64;
    for (int t = 0; t < NT; t++) {
        if (t + 1 < NT) { A_ISSUE(t + 1, buf ^ 1); cp_wait<1>(); }
        else            { cp_wait<0>(); }
        __syncthreads();
        const uint32_t* SKh = sm + buf * 6144;
        const uint32_t* SKl = SKh + 2048;
        const uint32_t* SV  = SKh + 4096;

        float sacc[8][4];
#pragma unroll
        for (int j = 0; j < 8; j++)
#pragma unroll
            for (int e = 0; e < 4; e++) sacc[j][e] = 0.f;
#pragma unroll
        for (int ks = 0; ks < 4; ks++) {
#pragma unroll
            for (int j = 0; j < 8; j++) {
                const uint2 kbh = *(const uint2*)(SKh + (j * 4 + ks) * 64 + (g * 4 + tq) * 2);
                const uint2 kbl = *(const uint2*)(SKl + (j * 4 + ks) * 64 + (g * 4 + tq) * 2);
                mma_f16(sacc[j], (const uint32_t*)&qh_[ks], (const uint32_t*)&kbh);
                mma_f16(sacc[j], (const uint32_t*)&qh_[ks], (const uint32_t*)&kbl);
                mma_f16(sacc[j], (const uint32_t*)&ql_[ks], (const uint32_t*)&kbh);
            }
        }

        float mx0 = -1e30f, mx1 = -1e30f;
#pragma unroll
        for (int j = 0; j < 8; j++) {
            mx0 = fmaxf(mx0, fmaxf(sacc[j][0], sacc[j][1]));
            mx1 = fmaxf(mx1, fmaxf(sacc[j][2], sacc[j][3]));
        }
        mx0 = fmaxf(mx0, __shfl_xor_sync(0xffffffffu, mx0, 1));
        mx0 = fmaxf(mx0, __shfl_xor_sync(0xffffffffu, mx0, 2));
        mx1 = fmaxf(mx1, __shfl_xor_sync(0xffffffffu, mx1, 1));
        mx1 = fmaxf(mx1, __shfl_xor_sync(0xffffffffu, mx1, 2));
        const float nm0 = fmaxf(m0, mx0), nm1 = fmaxf(m1, mx1);

        const bool upd = (nm0 != m0) || (nm1 != m1);
        if (__any_sync(0xffffffffu, upd)) {
            const float c0 = ex2(m0 - nm0), c1 = ex2(m1 - nm1);
            l0 *= c0; l1 *= c1;
#pragma unroll
            for (int j = 0; j < 8; j++) {
                oacc[j][0] *= c0; oacc[j][1] *= c0;
                oacc[j][2] *= c1; oacc[j][3] *= c1;
            }
            m0 = nm0; m1 = nm1;
        }

        uint32_t pc0 = 0, pc1 = 0;
#pragma unroll
        for (int k2 = 0; k2 < 4; k2++) {
            uint32_t pa[4];
            {
                const int j0 = 2 * k2, j1 = 2 * k2 + 1;
                const uint32_t a0 = ex2h2(sacc[j0][0] - m0, sacc[j0][1] - m0);
                const uint32_t a1 = ex2h2(sacc[j0][2] - m1, sacc[j0][3] - m1);
                const uint32_t a2 = ex2h2(sacc[j1][0] - m0, sacc[j1][1] - m0);
                const uint32_t a3 = ex2h2(sacc[j1][2] - m1, sacc[j1][3] - m1);
                pc0 = hadd2u(pc0, a0); pc1 = hadd2u(pc1, a1);
                pc0 = hadd2u(pc0, a2); pc1 = hadd2u(pc1, a3);
                pa[0] = a0; pa[1] = a1; pa[2] = a2; pa[3] = a3;
            }
#pragma unroll
            for (int j = 0; j < 8; j++) {
                const uint2 vb = *(const uint2*)(SV + (k2 * 8 + j) * 64 + (g * 4 + tq) * 2);
                mma_f16(oacc[j], pa, (const uint32_t*)&vb);
            }
        }

        const float2 f0 = h22f2(pc0), f1 = h22f2(pc1);
        float ls0 = f0.x + f0.y, ls1 = f1.x + f1.y;
        ls0 += __shfl_xor_sync(0xffffffffu, ls0, 1);
        ls0 += __shfl_xor_sync(0xffffffffu, ls0, 2);
        ls1 += __shfl_xor_sync(0xffffffffu, ls1, 1);
        ls1 += __shfl_xor_sync(0xffffffffu, ls1, 2);
        l0 += ls0; l1 += ls1;

        __syncthreads();
        buf ^= 1;
    }
#undef A_ISSUE

    const float inv0 = 1.0f / l0, inv1 = 1.0f / l1;
    const int mt_o = (bh >> 4) * 128 + blockIdx.x * 4 + warp;
#pragma unroll
    for (int j = 0; j < 8; j++) {
        const size_t ix0 = ((size_t)(mt_o * 64 + h * 4 + (j >> 1))) * 128 + (g * 4 + tq) * 4 + 2 * (j & 1);
        O16[ix0]     = pkh2(oacc[j][0] * inv0, oacc[j][1] * inv0);
        O16[ix0 + 1] = pkh2(oacc[j][2] * inv1, oacc[j][3] * inv1);
    }
}

// ---------------------------------------------------------------------------
// Launcher
// ---------------------------------------------------------------------------
#define SMEM_64K 65536
#define SMEM_ATT 49152

extern "C" void kernel_launch(void* const* d_in, const int* in_sizes, int n_in,
                              void* d_out, int out_size) {
    const float* x    = (const float*)d_in[0];
    const float* ln_w = (const float*)d_in[1];
    const float* ln_b = (const float*)d_in[2];
    const float* Wq   = (const float*)d_in[3];
    const float* Wkv  = (const float*)d_in[4];
    const float* qg   = (const float*)d_in[5];
    const float* kg   = (const float*)d_in[6];
    const float* Wo   = (const float*)d_in[7];
    float* out = (float*)d_out;

    uint32_t *xnh, *xnl, *xn16, *wqkh, *wqkl, *wv16, *wo16;
    uint32_t *qfh, *qfl, *kfh, *kfl, *vf, *ao16;
    cudaGetSymbolAddress((void**)&xnh,  g_xn_h);  cudaGetSymbolAddress((void**)&xnl,  g_xn_l);
    cudaGetSymbolAddress((void**)&xn16, g_xn16);
    cudaGetSymbolAddress((void**)&wqkh, g_wqk_h); cudaGetSymbolAddress((void**)&wqkl, g_wqk_l);
    cudaGetSymbolAddress((void**)&wv16, g_wv16);  cudaGetSymbolAddress((void**)&wo16, g_wo16);
    cudaGetSymbolAddress((void**)&qfh,  g_qf_h);  cudaGetSymbolAddress((void**)&qfl,  g_qf_l);
    cudaGetSymbolAddress((void**)&kfh,  g_kf_h);  cudaGetSymbolAddress((void**)&kfl,  g_kf_l);
    cudaGetSymbolAddress((void**)&vf,   g_vf);    cudaGetSymbolAddress((void**)&ao16, g_ao16);

    cudaFuncSetAttribute(proj_fused, cudaFuncAttributeMaxDynamicSharedMemorySize, SMEM_64K);
    cudaFuncSetAttribute(gemm_f16s,  cudaFuncAttributeMaxDynamicSharedMemorySize, SMEM_64K);
    cudaFuncSetAttribute(attn_bf,    cudaFuncAttributeMaxDynamicSharedMemorySize, SMEM_ATT);

    // prep: LN (4096 blocks) + coalesced weight conversion (1024 blocks)
    prep_kernel<<<TOK + 1024, 256>>>(x, ln_w, ln_b, xnh, xnl, xn16,
                                     Wq, Wkv, Wo, wqkh, wqkl, wv16, wo16);

    // fused QK (bf16x3) + V (fp16) projections + RMSNorm + fragment emission
    proj_fused<<<dim3(24, TOK / 128), 256, SMEM_64K>>>(xnh, xnl, xn16,
                                                       wqkh, wqkl, wv16,
                                                       qg, kg,
                                                       qfh, qfl, kfh, kfl, vf);

    attn_bf<<<dim3(Sq / 64, Bz * Hn), 128, SMEM_ATT>>>(qfh, qfl, kfh, kfl, vf, ao16);

    // output projection (fp16 single)
    gemm_f16s<<<dim3(DIM / 128, TOK / 128), 256, SMEM_64K>>>(ao16, wo16, out, DIM, INNER);
}

// round 17
// speedup vs baseline: 1.0206x; 1.0206x over previous
#include <cuda_runtime.h>
#include <cuda_bf16.h>
#include <cuda_fp16.h>
#include <cstdint>

#define Bz    2
#define Sq    2048
#define DIM   1024
#define Hn    16
#define DHd   64
#define INNER 1024
#define TOK   4096

// ---------------------------------------------------------------------------
// Scratch (device globals). Fragment arrays are uint32 (packed 16-bit x2).
// ---------------------------------------------------------------------------
__device__ uint32_t g_xn_h[TOK*DIM/2],     g_xn_l[TOK*DIM/2];   // bf16 hi/lo A-frags
__device__ uint32_t g_xn16[TOK*DIM/2];                          // fp16 single A-frags
__device__ uint32_t g_wqk_h[DIM*2048/2],   g_wqk_l[DIM*2048/2]; // Wq|Wk bf16 B-frags
__device__ uint32_t g_wv16[DIM*INNER/2];                        // Wv fp16 B-frags
__device__ uint32_t g_wo16[INNER*DIM/2];                        // Wo fp16 B-frags
__device__ uint32_t g_qf_h[TOK*INNER/2],   g_qf_l[TOK*INNER/2]; // fp16 hi/lo
__device__ uint32_t g_kf_h[TOK*INNER/2],   g_kf_l[TOK*INNER/2]; // fp16 hi/lo
__device__ uint32_t g_vf  [TOK*INNER/2];                        // fp16 single
__device__ uint32_t g_ao16[TOK*INNER/2];                        // attn out fp16 A-frags

#define LOG2E 1.4426950408889634f

// ---------------------------------------------------------------------------
// Helpers
// ---------------------------------------------------------------------------
__device__ __forceinline__ uint32_t smem_u32(const void* p) {
    uint32_t a;
    asm("{ .reg .u64 t; cvta.to.shared.u64 t, %1; cvt.u32.u64 %0, t; }" : "=r"(a) : "l"(p));
    return a;
}
__device__ __forceinline__ uint32_t pkbf(float a, float b) {
    return (uint32_t)__bfloat16_as_ushort(__float2bfloat16_rn(a)) |
           ((uint32_t)__bfloat16_as_ushort(__float2bfloat16_rn(b)) << 16);
}
__device__ __forceinline__ void splitbf(float a, float b, uint32_t& hi, uint32_t& lo) {
    __nv_bfloat16 ha = __float2bfloat16_rn(a), hb = __float2bfloat16_rn(b);
    hi = (uint32_t)__bfloat16_as_ushort(ha) | ((uint32_t)__bfloat16_as_ushort(hb) << 16);
    lo = pkbf(a - __bfloat162float(ha), b - __bfloat162float(hb));
}
__device__ __forceinline__ uint32_t pkh2(float a, float b) {
    __half2 h = __floats2half2_rn(a, b);
    return *(uint32_t*)&h;
}
__device__ __forceinline__ void splitf16(float a, float b, uint32_t& hi, uint32_t& lo) {
    __half ha = __float2half_rn(a), hb = __float2half_rn(b);
    __half2 hp = __halves2half2(ha, hb);
    hi = *(uint32_t*)&hp;
    lo = pkh2(a - __half2float(ha), b - __half2float(hb));
}
__device__ __forceinline__ float ex2(float x) {
    float y;
    asm("ex2.approx.f32 %0, %1;" : "=f"(y) : "f"(x));
    return y;
}
__device__ __forceinline__ uint32_t ex2h2(float a, float b) {
    uint32_t r;
    asm("{ .reg .b32 t; cvt.rn.f16x2.f32 t, %2, %1; ex2.approx.f16x2 %0, t; }"
        : "=r"(r) : "f"(a), "f"(b));
    return r;
}
__device__ __forceinline__ uint32_t hadd2u(uint32_t a, uint32_t b) {
    uint32_t r;
    asm("add.f16x2 %0, %1, %2;" : "=r"(r) : "r"(a), "r"(b));
    return r;
}
__device__ __forceinline__ float2 h22f2(uint32_t h) {
    __half2 hh = *(__half2*)&h;
    return __half22float2(hh);
}
__device__ __forceinline__ void mma_bf(float* c, const uint32_t* a, const uint32_t* b) {
    asm volatile(
        "mma.sync.aligned.m16n8k16.row.col.f32.bf16.bf16.f32 "
        "{%0,%1,%2,%3}, {%4,%5,%6,%7}, {%8,%9}, {%0,%1,%2,%3};"
        : "+f"(c[0]), "+f"(c[1]), "+f"(c[2]), "+f"(c[3])
        : "r"(a[0]), "r"(a[1]), "r"(a[2]), "r"(a[3]), "r"(b[0]), "r"(b[1]));
}
__device__ __forceinline__ void mma_f16(float* c, const uint32_t* a, const uint32_t* b) {
    asm volatile(
        "mma.sync.aligned.m16n8k16.row.col.f32.f16.f16.f32 "
        "{%0,%1,%2,%3}, {%4,%5,%6,%7}, {%8,%9}, {%0,%1,%2,%3};"
        : "+f"(c[0]), "+f"(c[1]), "+f"(c[2]), "+f"(c[3])
        : "r"(a[0]), "r"(a[1]), "r"(a[2]), "r"(a[3]), "r"(b[0]), "r"(b[1]));
}
__device__ __forceinline__ void cpa16(uint32_t saddr, const void* gptr) {
    asm volatile("cp.async.cg.shared.global [%0], [%1], 16;" :: "r"(saddr), "l"(gptr) : "memory");
}
__device__ __forceinline__ void cp_commit() { asm volatile("cp.async.commit_group;" ::: "memory"); }
template <int N> __device__ __forceinline__ void cp_wait() {
    asm volatile("cp.async.wait_group %0;" :: "n"(N) : "memory");
}

// ---------------------------------------------------------------------------
// 1) Prep: blocks [0,4096) LayerNorm; [4096,5120) coalesced weight frags.
// ---------------------------------------------------------------------------
__global__ void __launch_bounds__(256) prep_kernel(const float* __restrict__ x,
                                                   const float* __restrict__ w,
                                                   const float* __restrict__ bias,
                                                   uint32_t* __restrict__ xh,
                                                   uint32_t* __restrict__ xl,
                                                   uint32_t* __restrict__ x16,
                                                   const float* __restrict__ Wq,
                                                   const float* __restrict__ Wkv,
                                                   const float* __restrict__ Wo,
                                                   uint32_t* __restrict__ wqkh,
                                                   uint32_t* __restrict__ wqkl,
                                                   uint32_t* __restrict__ wv16,
                                                   uint32_t* __restrict__ wo16) {
    const int bid = blockIdx.x;
    if (bid >= TOK) {
        const int r = bid - TOK;
        const int mat = r >> 8;                // 0=Wq 1=Wk 2=Wv 3=Wo
        const int warp = threadIdx.x >> 5, lane = threadIdx.x & 31;
        const int gw = (r & 255) * 8 + warp;
        const int pb  = gw & 63;
        const int nt0 = (gw >> 6) << 2;
        const int ntl = lane >> 3, g = lane & 7;
        const int nt  = nt0 + ntl;
        const int n_local = nt * 8 + g;

        const float* src;
        int stride, col;
        if (mat == 0)      { src = Wq;  stride = 1024; col = n_local; }
        else if (mat == 1) { src = Wkv; stride = 2048; col = n_local; }
        else if (mat == 2) { src = Wkv; stride = 2048; col = 1024 + n_local; }
        else               { src = Wo;  stride = 1024; col = n_local; }

        float v[16];
#pragma unroll
        for (int i = 0; i < 16; i++)
            v[i] = src[(size_t)(16 * pb + i) * stride + col];

        if (mat <= 1) {
            uint32_t hiw[8], low[8];
#pragma unroll
            for (int o = 0; o < 8; o++) {
                const int pl = ((o & 1) << 2) + (o >> 1);
                splitbf(v[2 * pl], v[2 * pl + 1], hiw[o], low[o]);
            }
            const int out_nt = (mat == 0 ? 0 : 128) + nt;
            const size_t base = ((size_t)(out_nt * 64 + pb)) * 64 + g * 8;
            *(uint4*)(wqkh + base)     = make_uint4(hiw[0], hiw[1], hiw[2], hiw[3]);
            *(uint4*)(wqkh + base + 4) = make_uint4(hiw[4], hiw[5], hiw[6], hiw[7]);
            *(uint4*)(wqkl + base)     = make_uint4(low[0], low[1], low[2], low[3]);
            *(uint4*)(wqkl + base + 4) = make_uint4(low[4], low[5], low[6], low[7]);
        } else {
            uint32_t wd[8];
#pragma unroll
            for (int o = 0; o < 8; o++) {
                const int pl = ((o & 1) << 2) + (o >> 1);
                wd[o] = pkh2(v[2 * pl], v[2 * pl + 1]);
            }
            uint32_t* dst = (mat == 2) ? wv16 : wo16;
            const size_t base = ((size_t)(nt * 64 + pb)) * 64 + g * 8;
            *(uint4*)(dst + base)     = make_uint4(wd[0], wd[1], wd[2], wd[3]);
            *(uint4*)(dst + base + 4) = make_uint4(wd[4], wd[5], wd[6], wd[7]);
        }
        return;
    }
    const int row = bid;
    const float* xr = x + (size_t)row * DIM;
    float2 v[2];
    v[0] = *(const float2*)(xr + 2 * threadIdx.x);
    v[1] = *(const float2*)(xr + 2 * (threadIdx.x + 256));
    float s  = v[0].x + v[0].y + v[1].x + v[1].y;
    float sq = v[0].x * v[0].x + v[0].y * v[0].y + v[1].x * v[1].x + v[1].y * v[1].y;
#pragma unroll
    for (int off = 16; off; off >>= 1) {
        s  += __shfl_xor_sync(0xffffffffu, s, off);
        sq += __shfl_xor_sync(0xffffffffu, sq, off);
    }
    __shared__ float red[2][8];
    const int warp = threadIdx.x >> 5, lane = threadIdx.x & 31;
    if (lane == 0) { red[0][warp] = s; red[1][warp] = sq; }
    __syncthreads();
    float ts = 0.f, tq2 = 0.f;
#pragma unroll
    for (int i = 0; i < 8; i++) { ts += red[0][i]; tq2 += red[1][i]; }
    const float mean = ts * (1.0f / DIM);
    const float var  = tq2 * (1.0f / DIM) - mean * mean;
    const float rstd = rsqrtf(var + 1e-5f);
    const int mt = row >> 4, mr = row & 15, g = mr & 7, hih = mr >> 3;
#pragma unroll
    for (int i = 0; i < 2; i++) {
        const int p = threadIdx.x + i * 256;
        const float2 wv = *(const float2*)(w + 2 * p);
        const float2 bv = *(const float2*)(bias + 2 * p);
        const float y0 = wv.x * (v[i].x - mean) * rstd + bv.x;
        const float y1 = wv.y * (v[i].y - mean) * rstd + bv.y;
        const int ks = p >> 3, c = p & 7, tq = c & 3, ch = c >> 2;
        const size_t idx = ((size_t)(mt * 64 + ks)) * 128 + (g * 4 + tq) * 4 + hih + 2 * ch;
        uint32_t hi, lo;
        splitbf(y0, y1, hi, lo);
        xh[idx] = hi; xl[idx] = lo;
        x16[idx] = pkh2(y0, y1);
    }
}

// ---------------------------------------------------------------------------
// 2) Fused projection + RMSNorm + fragment emission. 3-stage pipelines.
// ---------------------------------------------------------------------------
__global__ void __launch_bounds__(256, 2) proj_fused(const uint32_t* __restrict__ Ah,
                                                     const uint32_t* __restrict__ Al,
                                                     const uint32_t* __restrict__ A16,
                                                     const uint32_t* __restrict__ Bh,
                                                     const uint32_t* __restrict__ Bl,
                                                     const uint32_t* __restrict__ Bv,
                                                     const float* __restrict__ qg,
                                                     const float* __restrict__ kg,
                                                     uint32_t* __restrict__ qfh,
                                                     uint32_t* __restrict__ qfl,
                                                     uint32_t* __restrict__ kfh,
                                                     uint32_t* __restrict__ kfl,
                                                     uint32_t* __restrict__ vf) {
    extern __shared__ uint32_t sm[];
    const int tid = threadIdx.x, wid = tid >> 5, lane = tid & 31;
    const int wr = wid >> 2, wc = wid & 3, g = lane >> 2, tq = lane & 3;
    const int bm = blockIdx.y * 128;
    const int b  = bm >> 11;
    const int sb = bm & 2047;
    const uint32_t sbase = smem_u32(sm);
    const int KS = 64;   // K = 1024

    float acc[4][4][4];
#pragma unroll
    for (int i = 0; i < 4; i++)
#pragma unroll
        for (int j = 0; j < 4; j++)
#pragma unroll
            for (int e = 0; e < 4; e++) acc[i][j][e] = 0.f;

    if (blockIdx.x < 16) {
        // ================= QK bf16x3 mainloop (BK=32, 3-stage) ============
        const int bn = blockIdx.x * 128;
        const uint32_t* Ah0 = Ah + (size_t)(bm >> 4) * KS * 128;
        const uint32_t* Al0 = Al + (size_t)(bm >> 4) * KS * 128;
        const uint32_t* Bh0 = Bh + (size_t)(bn >> 3) * KS * 64;
        const uint32_t* Bl0 = Bl + (size_t)(bn >> 3) * KS * 64;

#define G_ISSUE(S, BUF) do {                                                        \
    const uint32_t sb_ = sbase + (uint32_t)(BUF) * 32768u;                          \
    _Pragma("unroll")                                                               \
    for (int i_ = 0; i_ < 2; i_++) {                                                \
        const int f_ = tid + i_ * 256;                                              \
        const int mt_ = f_ >> 6, wA_ = (4 * f_) & 255;                              \
        const int ksA_ = wA_ >> 7, frA_ = wA_ & 127;                                \
        const size_t oa_ = ((size_t)mt_ * KS + (S) * 2 + ksA_) * 128 + frA_;        \
        cpa16(sb_ + f_ * 16u,           Ah0 + oa_);                                 \
        cpa16(sb_ + 8192u + f_ * 16u,   Al0 + oa_);                                 \
        const int nt_ = f_ >> 5, wB_ = (4 * f_) & 127;                              \
        const int ksB_ = wB_ >> 6, frB_ = wB_ & 63;                                 \
        const size_t ob_ = ((size_t)nt_ * KS + (S) * 2 + ksB_) * 64 + frB_;         \
        cpa16(sb_ + 16384u + f_ * 16u,  Bh0 + ob_);                                 \
        cpa16(sb_ + 24576u + f_ * 16u,  Bl0 + ob_);                                 \
    }                                                                               \
    cp_commit();                                                                    \
} while (0)

        G_ISSUE(0, 0);
        G_ISSUE(1, 1);
        for (int s = 0; s < 32; s++) {
            if (s + 1 < 32) cp_wait<1>(); else cp_wait<0>();
            __syncthreads();
            if (s + 2 < 32) G_ISSUE(s + 2, (s + 2) % 3);
            const uint32_t* S0 = sm + (s % 3) * 8192;
#pragma unroll
            for (int ksl = 0; ksl < 2; ksl++) {
                uint4 ah[4], al[4];
                uint2 bh2[4], bl2[4];
#pragma unroll
                for (int i = 0; i < 4; i++) {
                    const int mt = wr * 4 + i;
                    ah[i] = *(const uint4*)(S0 + (mt * 2 + ksl) * 128 + (g * 4 + tq) * 4);
                    al[i] = *(const uint4*)(S0 + 2048 + (mt * 2 + ksl) * 128 + (g * 4 + tq) * 4);
                }
#pragma unroll
                for (int j = 0; j < 4; j++) {
                    const int nt = wc * 4 + j;
                    bh2[j] = *(const uint2*)(S0 + 4096 + (nt * 2 + ksl) * 64 + (g * 4 + tq) * 2);
                    bl2[j] = *(const uint2*)(S0 + 6144 + (nt * 2 + ksl) * 64 + (g * 4 + tq) * 2);
                }
#pragma unroll
                for (int i = 0; i < 4; i++)
#pragma unroll
                    for (int j = 0; j < 4; j++) {
                        mma_bf(acc[i][j], (const uint32_t*)&ah[i], (const uint32_t*)&bh2[j]);
                        mma_bf(acc[i][j], (const uint32_t*)&ah[i], (const uint32_t*)&bl2[j]);
                        mma_bf(acc[i][j], (const uint32_t*)&al[i], (const uint32_t*)&bh2[j]);
                    }
            }
        }
#undef G_ISSUE
        __syncthreads();   // all warps done reading smem before reuse

        // ================= fused RMSNorm epilogue =========================
        float* part = (float*)sm;   // [4][128]
        float psum[4][2];
#pragma unroll
        for (int i = 0; i < 4; i++)
#pragma unroll
            for (int hih = 0; hih < 2; hih++) {
                float p = 0.f;
#pragma unroll
                for (int j = 0; j < 4; j++)
                    p += acc[i][j][2 * hih] * acc[i][j][2 * hih] +
                         acc[i][j][2 * hih + 1] * acc[i][j][2 * hih + 1];
                p += __shfl_xor_sync(0xffffffffu, p, 1);
                p += __shfl_xor_sync(0xffffffffu, p, 2);
                psum[i][hih] = p;
            }
        if (tq == 0) {
#pragma unroll
            for (int i = 0; i < 4; i++)
#pragma unroll
                for (int hih = 0; hih < 2; hih++)
                    part[wc * 128 + wr * 64 + i * 16 + g + 8 * hih] = psum[i][hih];
        }
        __syncthreads();
        float rsq[4][2];
#pragma unroll
        for (int i = 0; i < 4; i++)
#pragma unroll
            for (int hih = 0; hih < 2; hih++) {
                const int row = wr * 64 + i * 16 + g + 8 * hih;
                const float ss = part[wc * 128 + row] + part[(wc ^ 1) * 128 + row];
                rsq[i][hih] = rsqrtf(ss * (1.0f / 64.0f) + 1e-8f);
            }

        const bool isQ = (bn < 1024);
        const int h = ((isQ ? bn : bn - 1024) >> 6) + (wc >> 1);
        const int bh = b * 16 + h;

        if (isQ) {
#pragma unroll
            for (int i = 0; i < 4; i++) {
                const int mt = (sb >> 4) + wr * 4 + i;
#pragma unroll
                for (int ksl = 0; ksl < 2; ksl++) {
                    const int ks = (wc & 1) * 2 + ksl;
                    uint32_t hw[4], lw[4];
#pragma unroll
                    for (int w2 = 0; w2 < 4; w2++) {
                        const int hih = w2 & 1, ch = w2 >> 1;
                        const int j = 2 * ksl + ch;
                        const int dim = (wc & 1) * 32 + j * 8 + 2 * tq;
                        const float2 gv = *(const float2*)(qg + h * 64 + dim);
                        const float r = rsq[i][hih] * (8.0f * LOG2E);
                        splitf16(acc[i][j][2 * hih] * r * gv.x,
                                 acc[i][j][2 * hih + 1] * r * gv.y, hw[w2], lw[w2]);
                    }
                    const size_t base = ((size_t)((bh * 128 + mt) * 4 + ks)) * 128 + lane * 4;
                    *(uint4*)(qfh + base) = make_uint4(hw[0], hw[1], hw[2], hw[3]);
                    *(uint4*)(qfl + base) = make_uint4(lw[0], lw[1], lw[2], lw[3]);
                }
            }
        } else {
#pragma unroll
            for (int i = 0; i < 4; i++)
#pragma unroll
                for (int hih = 0; hih < 2; hih++) {
                    const int nt = (sb >> 3) + (wr * 4 + i) * 2 + hih;
#pragma unroll
                    for (int ksl = 0; ksl < 2; ksl++) {
                        const int ks = (wc & 1) * 2 + ksl;
                        uint32_t hw[2], lw[2];
#pragma unroll
                        for (int ch = 0; ch < 2; ch++) {
                            const int j = 2 * ksl + ch;
                            const int dim = (wc & 1) * 32 + j * 8 + 2 * tq;
                            const float2 gv = *(const float2*)(kg + h * 64 + dim);
                            const float r = rsq[i][hih] * 8.0f;
                            splitf16(acc[i][j][2 * hih] * r * gv.x,
                                     acc[i][j][2 * hih + 1] * r * gv.y, hw[ch], lw[ch]);
                        }
                        const size_t base = ((size_t)((bh * 256 + nt) * 4 + ks)) * 64 + lane * 2;
                        *(uint2*)(kfh + base) = make_uint2(hw[0], hw[1]);
                        *(uint2*)(kfl + base) = make_uint2(lw[0], lw[1]);
                    }
                }
        }
    } else {
        // ================= V fp16 mainloop (BK=64, 3-stage) ===============
        const int bn = (blockIdx.x - 16) * 128;
        const uint32_t* A0g = A16 + (size_t)(bm >> 4) * KS * 128;
        const uint32_t* B0g = Bv + (size_t)(bn >> 3) * KS * 64;

#define F_ISSUE(S, BUF) do {                                                        \
    const uint32_t sb_ = sbase + (uint32_t)(BUF) * 32768u;                          \
    _Pragma("unroll")                                                               \
    for (int i_ = 0; i_ < 4; i_++) {                                                \
        const int f_ = tid + i_ * 256;                                              \
        const int mt_ = f_ >> 7, wA_ = (4 * f_) & 511;                              \
        const int ksA_ = wA_ >> 7, frA_ = wA_ & 127;                                \
        const size_t oa_ = ((size_t)mt_ * KS + (S) * 4 + ksA_) * 128 + frA_;        \
        cpa16(sb_ + f_ * 16u, A0g + oa_);                                           \
        const int nt_ = f_ >> 6, wB_ = (4 * f_) & 255;                              \
        const int ksB_ = wB_ >> 6, frB_ = wB_ & 63;                                 \
        const size_t ob_ = ((size_t)nt_ * KS + (S) * 4 + ksB_) * 64 + frB_;         \
        cpa16(sb_ + 16384u + f_ * 16u, B0g + ob_);                                  \
    }                                                                               \
    cp_commit();                                                                    \
} while (0)

        F_ISSUE(0, 0);
        F_ISSUE(1, 1);
        for (int s = 0; s < 16; s++) {
            if (s + 1 < 16) cp_wait<1>(); else cp_wait<0>();
            __syncthreads();
            if (s + 2 < 16) F_ISSUE(s + 2, (s + 2) % 3);
            const uint32_t* S0 = sm + (s % 3) * 8192;
#pragma unroll
            for (int ksl = 0; ksl < 4; ksl++) {
                uint4 a[4];
                uint2 b2[4];
#pragma unroll
                for (int i = 0; i < 4; i++)
                    a[i] = *(const uint4*)(S0 + ((wr * 4 + i) * 4 + ksl) * 128 + (g * 4 + tq) * 4);
#pragma unroll
                for (int j = 0; j < 4; j++)
                    b2[j] = *(const uint2*)(S0 + 4096 + ((wc * 4 + j) * 4 + ksl) * 64 + (g * 4 + tq) * 2);
#pragma unroll
                for (int i = 0; i < 4; i++)
#pragma unroll
                    for (int j = 0; j < 4; j++)
                        mma_f16(acc[i][j], (const uint32_t*)&a[i], (const uint32_t*)&b2[j]);
            }
        }
#undef F_ISSUE

        // ================= V transpose epilogue -> vf B-frags =============
        __syncthreads();
        __half* vsm = (__half*)sm;     // [128][136]
#pragma unroll
        for (int i = 0; i < 4; i++)
#pragma unroll
            for (int j = 0; j < 4; j++)
#pragma unroll
                for (int e = 0; e < 4; e++) {
                    const int row = wr * 64 + i * 16 + g + 8 * (e >> 1);
                    const int col = wc * 32 + j * 8 + 2 * tq + (e & 1);
                    vsm[row * 136 + col] = __float2half_rn(acc[i][j][e]);
                }
        __syncthreads();
        const int h0 = bn >> 6;
        const int ksv = (sb >> 4) + wid;
        const int dl = lane >> 2, tv = lane & 3;
#pragma unroll
        for (int hh = 0; hh < 2; hh++) {
            const int bh = b * 16 + h0 + hh;
#pragma unroll
            for (int ntd = 0; ntd < 8; ntd++) {
                uint32_t w2[2];
#pragma unroll
                for (int rv = 0; rv < 2; rv++) {
                    const int rloc = 16 * wid + 8 * rv + 2 * tv;
                    const int col = hh * 64 + ntd * 8 + dl;
                    const __half va = vsm[rloc * 136 + col];
                    const __half vb = vsm[(rloc + 1) * 136 + col];
                    const __half2 hp = __halves2half2(va, vb);
                    w2[rv] = *(const uint32_t*)&hp;
                }
                const size_t base = ((size_t)((bh * 128 + ksv) * 8 + ntd)) * 64 + lane * 2;
                *(uint2*)(vf + base) = make_uint2(w2[0], w2[1]);
            }
        }
    }
}

// ---------------------------------------------------------------------------
// 3) Output projection: fp16-single GEMM, 3-stage pipeline, fp32 C.
// ---------------------------------------------------------------------------
__global__ void __launch_bounds__(256, 2) gemm_f16s(const uint32_t* __restrict__ Af,
                                                    const uint32_t* __restrict__ Bf,
                                                    float* __restrict__ C,
                                                    int N, int K) {
    extern __shared__ uint32_t sm[];
    const int tid = threadIdx.x, wid = tid >> 5, lane = tid & 31;
    const int wr = wid >> 2, wc = wid & 3, g = lane >> 2, tq = lane & 3;
    const int bm = blockIdx.y * 128, bn = blockIdx.x * 128;
    const int KS = K >> 4, NSTG = K >> 6;
    const uint32_t sbase = smem_u32(sm);

    const uint32_t* A0g = Af + (size_t)(bm >> 4) * KS * 128;
    const uint32_t* B0g = Bf + (size_t)(bn >> 3) * KS * 64;

    float acc[4][4][4];
#pragma unroll
    for (int i = 0; i < 4; i++)
#pragma unroll
        for (int j = 0; j < 4; j++)
#pragma unroll
            for (int e = 0; e < 4; e++) acc[i][j][e] = 0.f;

#define F_ISSUE(S, BUF) do {                                                        \
    const uint32_t sb_ = sbase + (uint32_t)(BUF) * 32768u;                          \
    _Pragma("unroll")                                                               \
    for (int i_ = 0; i_ < 4; i_++) {                                                \
        const int f_ = tid + i_ * 256;                                              \
        const int mt_ = f_ >> 7, wA_ = (4 * f_) & 511;                              \
        const int ksA_ = wA_ >> 7, frA_ = wA_ & 127;                                \
        const size_t oa_ = ((size_t)mt_ * KS + (S) * 4 + ksA_) * 128 + frA_;        \
        cpa16(sb_ + f_ * 16u, A0g + oa_);                                           \
        const int nt_ = f_ >> 6, wB_ = (4 * f_) & 255;                              \
        const int ksB_ = wB_ >> 6, frB_ = wB_ & 63;                                 \
        const size_t ob_ = ((size_t)nt_ * KS + (S) * 4 + ksB_) * 64 + frB_;         \
        cpa16(sb_ + 16384u + f_ * 16u, B0g + ob_);                                  \
    }                                                                               \
    cp_commit();                                                                    \
} while (0)

    F_ISSUE(0, 0);
    F_ISSUE(1, 1);
    for (int s = 0; s < NSTG; s++) {
        if (s + 1 < NSTG) cp_wait<1>(); else cp_wait<0>();
        __syncthreads();
        if (s + 2 < NSTG) F_ISSUE(s + 2, (s + 2) % 3);
        const uint32_t* S0 = sm + (s % 3) * 8192;
#pragma unroll
        for (int ksl = 0; ksl < 4; ksl++) {
            uint4 a[4];
            uint2 b2[4];
#pragma unroll
            for (int i = 0; i < 4; i++)
                a[i] = *(const uint4*)(S0 + ((wr * 4 + i) * 4 + ksl) * 128 + (g * 4 + tq) * 4);
#pragma unroll
            for (int j = 0; j < 4; j++)
                b2[j] = *(const uint2*)(S0 + 4096 + ((wc * 4 + j) * 4 + ksl) * 64 + (g * 4 + tq) * 2);
#pragma unroll
            for (int i = 0; i < 4; i++)
#pragma unroll
                for (int j = 0; j < 4; j++)
                    mma_f16(acc[i][j], (const uint32_t*)&a[i], (const uint32_t*)&b2[j]);
        }
    }
#undef F_ISSUE

#pragma unroll
    for (int i = 0; i < 4; i++) {
        const int r0 = bm + (wr * 4 + i) * 16 + g;
#pragma unroll
        for (int j = 0; j < 4; j++) {
            const int c0 = bn + (wc * 4 + j) * 8 + 2 * tq;
            *(float2*)(C + (size_t)r0 * N + c0)       = make_float2(acc[i][j][0], acc[i][j][1]);
            *(float2*)(C + (size_t)(r0 + 8) * N + c0) = make_float2(acc[i][j][2], acc[i][j][3]);
        }
    }
}

// ---------------------------------------------------------------------------
// 4) Flash attention (unchanged).
// ---------------------------------------------------------------------------
__global__ void __launch_bounds__(128, 4) attn_bf(const uint32_t* __restrict__ Qh,
                                                  const uint32_t* __restrict__ Ql,
                                                  const uint32_t* __restrict__ Kh,
                                                  const uint32_t* __restrict__ Kl,
                                                  const uint32_t* __restrict__ Vf,
                                                  uint32_t* __restrict__ O16) {
    extern __shared__ uint32_t sm[];
    const int tid = threadIdx.x, warp = tid >> 5, lane = tid & 31;
    const int g = lane >> 2, tq = lane & 3;
    const int bh = blockIdx.y, h = bh & 15;
    const uint32_t sbase = smem_u32(sm);

    uint4 qh_[4], ql_[4];
    {
        const size_t qb = ((size_t)(bh * 128 + blockIdx.x * 4 + warp)) * 4;
#pragma unroll
        for (int ks = 0; ks < 4; ks++) {
            qh_[ks] = *(const uint4*)(Qh + (qb + ks) * 128 + (g * 4 + tq) * 4);
            ql_[ks] = *(const uint4*)(Ql + (qb + ks) * 128 + (g * 4 + tq) * 4);
        }
    }

    const uint32_t* Kh0 = Kh + (size_t)bh * 65536;
    const uint32_t* Kl0 = Kl + (size_t)bh * 65536;
    const uint32_t* Vf0 = Vf + (size_t)bh * 65536;

    float oacc[8][4];
#pragma unroll
    for (int j = 0; j < 8; j++)
#pragma unroll
        for (int e = 0; e < 4; e++) oacc[j][e] = 0.f;
    float m0 = -1e30f, m1 = -1e30f, l0 = 0.f, l1 = 0.f;

#define A_ISSUE(T, BUF) do {                                                  \
    const uint32_t sb_ = sbase + (uint32_t)(BUF) * 24576u;                    \
    _Pragma("unroll")                                                         \
    for (int i_ = 0; i_ < 4; i_++) {                                          \
        const int f_ = tid + i_ * 128;                                        \
        const size_t o_ = (size_t)(T) * 2048 + 4 * f_;                        \
        cpa16(sb_ + f_ * 16u,          Kh0 + o_);                             \
        cpa16(sb_ + 8192u + f_ * 16u,  Kl0 + o_);                             \
        cpa16(sb_ + 16384u + f_ * 16u, Vf0 + o_);                             \
    }                                                                         \
    cp_commit();                                                              \
} while (0)

    A_ISSUE(0, 0);
    int buf = 0;
    const int NT = Sq / 64;
    for (int t = 0; t < NT; t++) {
        if (t + 1 < NT) { A_ISSUE(t + 1, buf ^ 1); cp_wait<1>(); }
        else            { cp_wait<0>(); }
        __syncthreads();
        const uint32_t* SKh = sm + buf * 6144;
        const uint32_t* SKl = SKh + 2048;
        const uint32_t* SV  = SKh + 4096;

        float sacc[8][4];
#pragma unroll
        for (int j = 0; j < 8; j++)
#pragma unroll
            for (int e = 0; e < 4; e++) sacc[j][e] = 0.f;
#pragma unroll
        for (int ks = 0; ks < 4; ks++) {
#pragma unroll
            for (int j = 0; j < 8; j++) {
                const uint2 kbh = *(const uint2*)(SKh + (j * 4 + ks) * 64 + (g * 4 + tq) * 2);
                const uint2 kbl = *(const uint2*)(SKl + (j * 4 + ks) * 64 + (g * 4 + tq) * 2);
                mma_f16(sacc[j], (const uint32_t*)&qh_[ks], (const uint32_t*)&kbh);
                mma_f16(sacc[j], (const uint32_t*)&qh_[ks], (const uint32_t*)&kbl);
                mma_f16(sacc[j], (const uint32_t*)&ql_[ks], (const uint32_t*)&kbh);
            }
        }

        float mx0 = -1e30f, mx1 = -1e30f;
#pragma unroll
        for (int j = 0; j < 8; j++) {
            mx0 = fmaxf(mx0, fmaxf(sacc[j][0], sacc[j][1]));
            mx1 = fmaxf(mx1, fmaxf(sacc[j][2], sacc[j][3]));
        }
        mx0 = fmaxf(mx0, __shfl_xor_sync(0xffffffffu, mx0, 1));
        mx0 = fmaxf(mx0, __shfl_xor_sync(0xffffffffu, mx0, 2));
        mx1 = fmaxf(mx1, __shfl_xor_sync(0xffffffffu, mx1, 1));
        mx1 = fmaxf(mx1, __shfl_xor_sync(0xffffffffu, mx1, 2));
        const float nm0 = fmaxf(m0, mx0), nm1 = fmaxf(m1, mx1);

        const bool upd = (nm0 != m0) || (nm1 != m1);
        if (__any_sync(0xffffffffu, upd)) {
            const float c0 = ex2(m0 - nm0), c1 = ex2(m1 - nm1);
            l0 *= c0; l1 *= c1;
#pragma unroll
            for (int j = 0; j < 8; j++) {
                oacc[j][0] *= c0; oacc[j][1] *= c0;
                oacc[j][2] *= c1; oacc[j][3] *= c1;
            }
            m0 = nm0; m1 = nm1;
        }

        uint32_t pc0 = 0, pc1 = 0;
#pragma unroll
        for (int k2 = 0; k2 < 4; k2++) {
            uint32_t pa[4];
            {
                const int j0 = 2 * k2, j1 = 2 * k2 + 1;
                const uint32_t a0 = ex2h2(sacc[j0][0] - m0, sacc[j0][1] - m0);
                const uint32_t a1 = ex2h2(sacc[j0][2] - m1, sacc[j0][3] - m1);
                const uint32_t a2 = ex2h2(sacc[j1][0] - m0, sacc[j1][1] - m0);
                const uint32_t a3 = ex2h2(sacc[j1][2] - m1, sacc[j1][3] - m1);
                pc0 = hadd2u(pc0, a0); pc1 = hadd2u(pc1, a1);
                pc0 = hadd2u(pc0, a2); pc1 = hadd2u(pc1, a3);
                pa[0] = a0; pa[1] = a1; pa[2] = a2; pa[3] = a3;
            }
#pragma unroll
            for (int j = 0; j < 8; j++) {
                const uint2 vb = *(const uint2*)(SV + (k2 * 8 + j) * 64 + (g * 4 + tq) * 2);
                mma_f16(oacc[j], pa, (const uint32_t*)&vb);
            }
        }

        const float2 f0 = h22f2(pc0), f1 = h22f2(pc1);
        float ls0 = f0.x + f0.y, ls1 = f1.x + f1.y;
        ls0 += __shfl_xor_sync(0xffffffffu, ls0, 1);
        ls0 += __shfl_xor_sync(0xffffffffu, ls0, 2);
        ls1 += __shfl_xor_sync(0xffffffffu, ls1, 1);
        ls1 += __shfl_xor_sync(0xffffffffu, ls1, 2);
        l0 += ls0; l1 += ls1;

        __syncthreads();
        buf ^= 1;
    }
#undef A_ISSUE

    const float inv0 = 1.0f / l0, inv1 = 1.0f / l1;
    const int mt_o = (bh >> 4) * 128 + blockIdx.x * 4 + warp;
#pragma unroll
    for (int j = 0; j < 8; j++) {
        const size_t ix0 = ((size_t)(mt_o * 64 + h * 4 + (j >> 1))) * 128 + (g * 4 + tq) * 4 + 2 * (j & 1);
        O16[ix0]     = pkh2(oacc[j][0] * inv0, oacc[j][1] * inv0);
        O16[ix0 + 1] = pkh2(oacc[j][2] * inv1, oacc[j][3] * inv1);
    }
}

// ---------------------------------------------------------------------------
// Launcher
// ---------------------------------------------------------------------------
#define SMEM_96K 98304
#define SMEM_ATT 49152

extern "C" void kernel_launch(void* const* d_in, const int* in_sizes, int n_in,
                              void* d_out, int out_size) {
    const float* x    = (const float*)d_in[0];
    const float* ln_w = (const float*)d_in[1];
    const float* ln_b = (const float*)d_in[2];
    const float* Wq   = (const float*)d_in[3];
    const float* Wkv  = (const float*)d_in[4];
    const float* qg   = (const float*)d_in[5];
    const float* kg   = (const float*)d_in[6];
    const float* Wo   = (const float*)d_in[7];
    float* out = (float*)d_out;

    uint32_t *xnh, *xnl, *xn16, *wqkh, *wqkl, *wv16, *wo16;
    uint32_t *qfh, *qfl, *kfh, *kfl, *vf, *ao16;
    cudaGetSymbolAddress((void**)&xnh,  g_xn_h);  cudaGetSymbolAddress((void**)&xnl,  g_xn_l);
    cudaGetSymbolAddress((void**)&xn16, g_xn16);
    cudaGetSymbolAddress((void**)&wqkh, g_wqk_h); cudaGetSymbolAddress((void**)&wqkl, g_wqk_l);
    cudaGetSymbolAddress((void**)&wv16, g_wv16);  cudaGetSymbolAddress((void**)&wo16, g_wo16);
    cudaGetSymbolAddress((void**)&qfh,  g_qf_h);  cudaGetSymbolAddress((void**)&qfl,  g_qf_l);
    cudaGetSymbolAddress((void**)&kfh,  g_kf_h);  cudaGetSymbolAddress((void**)&kfl,  g_kf_l);
    cudaGetSymbolAddress((void**)&vf,   g_vf);    cudaGetSymbolAddress((void**)&ao16, g_ao16);

    cudaFuncSetAttribute(proj_fused, cudaFuncAttributeMaxDynamicSharedMemorySize, SMEM_96K);
    cudaFuncSetAttribute(gemm_f16s,  cudaFuncAttributeMaxDynamicSharedMemorySize, SMEM_96K);
    cudaFuncSetAttribute(attn_bf,    cudaFuncAttributeMaxDynamicSharedMemorySize, SMEM_ATT);

    // prep: LN (4096 blocks) + coalesced weight conversion (1024 blocks)
    prep_kernel<<<TOK + 1024, 256>>>(x, ln_w, ln_b, xnh, xnl, xn16,
                                     Wq, Wkv, Wo, wqkh, wqkl, wv16, wo16);

    // fused QK (bf16x3) + V (fp16) projections + RMSNorm + fragment emission
    proj_fused<<<dim3(24, TOK / 128), 256, SMEM_96K>>>(xnh, xnl, xn16,
                                                       wqkh, wqkl, wv16,
                                                       qg, kg,
                                                       qfh, qfl, kfh, kfl, vf);

    attn_bf<<<dim3(Sq / 64, Bz * Hn), 128, SMEM_ATT>>>(qfh, qfl, kfh, kfl, vf, ao16);

    // output projection (fp16 single)
    gemm_f16s<<<dim3(DIM / 128, TOK / 128), 256, SMEM_96K>>>(ao16, wo16, out, DIM, INNER);
}